// round 2
// baseline (speedup 1.0000x reference)
#include <cuda_runtime.h>

#define PQ   150000
#define NGT  256
#define NC   80
#define TK   13
#define CP   512           // priors per stage1 block
#define SC   64            // sub-chunk staged in smem
#define NSUB (CP / SC)
#define NCH  ((PQ + CP - 1) / CP)   // 293 chunks
#define EPSF 1e-9f

// ---- device scratch (no allocations allowed) ----
__device__ unsigned long long g_cand[(size_t)NGT * NCH * TK]; // per-(gt,chunk) top-13 keys
__device__ int g_topk[NGT * TK];   // final per-gt top-13 prior indices (-1 if row dropped)
__device__ int g_cnt[PQ];          // how many gts picked this prior
__device__ int g_first[PQ];        // min gt index that picked this prior
__device__ int g_labm1[PQ];        // assigned label-1 per prior (for one-hot kernel)

static __device__ __forceinline__ unsigned long long umax64(unsigned long long a, unsigned long long b) {
    return a > b ? a : b;
}

__global__ void k_init() {
    int p = blockIdx.x * blockDim.x + threadIdx.x;
    if (p < PQ) { g_cnt[p] = 0; g_first[p] = 0x7FFFFFFF; }
}

// Stage 1: thread g owns gt g; block processes CP priors in SC-sized smem tiles.
// cls_pred read exactly once (coalesced float4, transposed into smem);
// bbox_pred read exactly once.
__global__ __launch_bounds__(NGT) void k_stage1(const float*  __restrict__ cls,
                                                const float4* __restrict__ pbox,
                                                const int*    __restrict__ lblg,
                                                const float4* __restrict__ gbox) {
    __shared__ float  s_cls[NC * (SC + 1)];
    __shared__ float4 s_box[SC];
    __shared__ float  s_area[SC];

    const int g = threadIdx.x;
    const int chunk = blockIdx.x;
    const int pbase0 = chunk * CP;

    float4 gb = gbox[g];
    const int cg = lblg[g] - 1;
    const float ga = fmaxf(gb.z - gb.x, 0.f) * fmaxf(gb.w - gb.y, 0.f);

    unsigned long long top[TK];
#pragma unroll
    for (int j = 0; j < TK; j++) top[j] = 0ULL;

    for (int sc = 0; sc < NSUB; sc++) {
        const int pbase = pbase0 + sc * SC;
        __syncthreads();
        // stage prior boxes + areas
        if (threadIdx.x < SC) {
            int p = pbase + threadIdx.x;
            float4 b = (p < PQ) ? pbox[p] : make_float4(0.f, 0.f, 0.f, 0.f);
            s_box[threadIdx.x] = b;
            s_area[threadIdx.x] = fmaxf(b.z - b.x, 0.f) * fmaxf(b.w - b.y, 0.f);
        }
        // stage cls tile, transposed: s_cls[col][row]
        for (int q = threadIdx.x; q < SC * (NC / 4); q += NGT) {
            int r  = q / (NC / 4);
            int c4 = q - r * (NC / 4);
            int p  = pbase + r;
            float4 v = (p < PQ) ? *(const float4*)(cls + (size_t)p * NC + c4 * 4)
                                : make_float4(0.f, 0.f, 0.f, 0.f);
            s_cls[(c4 * 4 + 0) * (SC + 1) + r] = v.x;
            s_cls[(c4 * 4 + 1) * (SC + 1) + r] = v.y;
            s_cls[(c4 * 4 + 2) * (SC + 1) + r] = v.z;
            s_cls[(c4 * 4 + 3) * (SC + 1) + r] = v.w;
        }
        __syncthreads();

#pragma unroll 4
        for (int r = 0; r < SC; r++) {
            float4 b = s_box[r];               // broadcast LDS.128
            float a2 = s_area[r];
            float s  = s_cls[cg * (SC + 1) + r];
            float x1 = fmaxf(gb.x, b.x), y1 = fmaxf(gb.y, b.y);
            float x2 = fminf(gb.z, b.z), y2 = fminf(gb.w, b.w);
            float iw = fmaxf(x2 - x1, 0.f), ih = fmaxf(y2 - y1, 0.f);
            float inter = iw * ih;
            float iou = inter / (ga + a2 - inter + EPSF);
            float i2 = iou * iou;
            float m = s * (i2 * i2 * i2);      // score^1 * iou^6
            int p = pbase + r;
            // key: (value desc, index asc) packed so larger key == better
            unsigned long long key =
                ((unsigned long long)__float_as_uint(m) << 32) | (unsigned)(~(unsigned)p);
            if (p < PQ && key > top[0]) {
                top[0] = key;
#pragma unroll
                for (int j = 0; j < TK - 1; j++) {
                    if (top[j] > top[j + 1]) {
                        unsigned long long t = top[j]; top[j] = top[j + 1]; top[j + 1] = t;
                    }
                }
            }
        }
    }
    unsigned long long* dst = &g_cand[((size_t)g * NCH + chunk) * TK];
#pragma unroll
    for (int j = 0; j < TK; j++) dst[j] = top[j];
}

// Stage 2: one block per gt, merge NCH*TK candidates -> global top-13.
// All real keys are unique (index in low word), so argmax rounds are unambiguous.
__global__ __launch_bounds__(256) void k_stage2() {
    __shared__ unsigned long long s_c[NCH * TK];   // 30472 B
    __shared__ unsigned long long s_red[256];
    __shared__ int s_keep;
    const int g = blockIdx.x;
    const int tid = threadIdx.x;
    const int M = NCH * TK;
    for (int i = tid; i < M; i += 256) s_c[i] = g_cand[(size_t)g * M + i];
    __syncthreads();

    for (int round = 0; round < TK; round++) {
        unsigned long long lm = 0ULL;
        for (int i = tid; i < M; i += 256) lm = umax64(lm, s_c[i]);
        s_red[tid] = lm;
        __syncthreads();
        for (int off = 128; off > 0; off >>= 1) {
            if (tid < off) s_red[tid] = umax64(s_red[tid], s_red[tid + off]);
            __syncthreads();
        }
        unsigned long long mk = s_red[0];
        if (round == 0 && tid == 0)
            s_keep = (__uint_as_float((unsigned)(mk >> 32)) > EPSF) ? 1 : 0;
        for (int i = tid; i < M; i += 256)
            if (s_c[i] == mk) s_c[i] = 0ULL;   // unique -> removed once
        if (tid == 0)
            g_topk[g * TK + round] = (int)(~(unsigned)mk);
        __syncthreads();
    }
    if (tid < TK && s_keep == 0) g_topk[g * TK + tid] = -1;
}

// Scatter: count picks per prior + min gt per prior.
__global__ void k_scatter() {
    int i = blockIdx.x * blockDim.x + threadIdx.x;
    if (i >= NGT * TK) return;
    int p = g_topk[i];
    if (p >= 0) {
        atomicAdd(&g_cnt[p], 1);
        atomicMin(&g_first[p], i / TK);
    }
}

// Final per-prior resolution + writes of gt_idx, labels, bboxes.
__global__ __launch_bounds__(256) void k_final(const float4* __restrict__ pbox,
                                               const int*    __restrict__ lblg,
                                               const float4* __restrict__ gbox,
                                               float*        __restrict__ out) {
    __shared__ float4 s_g[NGT];
    __shared__ float  s_ga[NGT];
    const int tid = threadIdx.x;
    {
        float4 q = gbox[tid];
        s_g[tid] = q;
        s_ga[tid] = fmaxf(q.z - q.x, 0.f) * fmaxf(q.w - q.y, 0.f);
    }
    __syncthreads();
    const int p = blockIdx.x * 256 + tid;
    if (p >= PQ) return;

    const int c = g_cnt[p];
    int gt = 0;
    if (c == 1) {
        gt = g_first[p];
    } else if (c > 1) {
        // conflict: argmax over gts of iou (ties -> lowest g). Rare path (<3328 priors total).
        float4 b = pbox[p];
        float a2 = fmaxf(b.z - b.x, 0.f) * fmaxf(b.w - b.y, 0.f);
        float best = -1.f; int bg = 0;
        for (int g = 0; g < NGT; g++) {
            float4 gb = s_g[g];
            float x1 = fmaxf(gb.x, b.x), y1 = fmaxf(gb.y, b.y);
            float x2 = fminf(gb.z, b.z), y2 = fminf(gb.w, b.w);
            float iw = fmaxf(x2 - x1, 0.f), ih = fmaxf(y2 - y1, 0.f);
            float inter = iw * ih;
            float iou = inter / (s_ga[g] + a2 - inter + EPSF);
            if (iou > best) { best = iou; bg = g; }
        }
        gt = bg;
    }
    const int lab = lblg[gt];
    out[p] = (float)gt;                              // assigned_gt_index
    out[(size_t)PQ + p] = (c > 0) ? (float)lab : 0.f; // assigned_labels (zeroed if unassigned)
    g_labm1[p] = lab - 1;                            // one-hot uses pre-zeroed label
    // assigned_bboxes (always gt's box, gt=0 when unassigned — matches reference)
    ((float4*)(out + 2 * (size_t)PQ + (size_t)NC * PQ))[p] = s_g[gt];
}

// One-hot cls: fully coalesced float4 stores of the 48 MB block.
__global__ void k_cls(float* __restrict__ out) {
    int i = blockIdx.x * blockDim.x + threadIdx.x;
    if (i >= PQ * (NC / 4)) return;
    int p  = i / (NC / 4);
    int q4 = i - p * (NC / 4);
    int lm = g_labm1[p];
    int base = q4 * 4;
    float4 v;
    v.x = (lm == base + 0) ? 1.f : 0.f;
    v.y = (lm == base + 1) ? 1.f : 0.f;
    v.z = (lm == base + 2) ? 1.f : 0.f;
    v.w = (lm == base + 3) ? 1.f : 0.f;
    ((float4*)(out + 2 * (size_t)PQ))[i] = v;
}

extern "C" void kernel_launch(void* const* d_in, const int* in_sizes, int n_in,
                              void* d_out, int out_size) {
    const float*  cls  = (const float*)d_in[0];   // [P,80]
    const float4* pbox = (const float4*)d_in[1];  // [P,4]
    const int*    lblg = (const int*)d_in[2];     // [N,1]
    const float4* gbox = (const float4*)d_in[3];  // [N,4]
    float* out = (float*)d_out;

    k_init<<<(PQ + 255) / 256, 256>>>();
    k_stage1<<<NCH, NGT>>>(cls, pbox, lblg, gbox);
    k_stage2<<<NGT, 256>>>();
    k_scatter<<<(NGT * TK + 255) / 256, 256>>>();
    k_final<<<(PQ + 255) / 256, 256>>>(pbox, lblg, gbox, out);
    k_cls<<<(PQ * (NC / 4) + 255) / 256, 256>>>(out);
}

// round 5
// speedup vs baseline: 1.3666x; 1.3666x over previous
#include <cuda_runtime.h>

#define PQ   150000
#define NGT  256
#define NC   80
#define TK   13
#define CHK  4096                      // priors per stage1 chunk
#define SUB  1024                      // smem box sub-tile
#define NCH  ((PQ + CHK - 1) / CHK)    // 37 chunks
#define M2   (NCH * TK)                // 481 candidates per gt
#define GPB  8                         // gts (warps) per stage1 block
#define EPSF 1e-9f
#define FULL 0xFFFFFFFFu

// ---- device scratch (no allocations allowed) ----
__device__ float g_clsT[(size_t)NC * PQ];                 // class-major transpose (48MB)
__device__ unsigned long long g_cand[(size_t)NGT * M2];   // per-(gt,chunk) top-13 keys
__device__ int g_cnt[PQ];
__device__ int g_first[PQ];
__device__ int g_labm1[PQ];

static __device__ __forceinline__ unsigned long long umax64(unsigned long long a, unsigned long long b) {
    return a > b ? a : b;
}

__global__ void k_init() {
    int p = blockIdx.x * blockDim.x + threadIdx.x;
    if (p < PQ) { g_cnt[p] = 0; g_first[p] = 0x7FFFFFFF; }
}

// Transpose cls [P,80] -> clsT [80,P]. Block handles 32 priors; coalesced both ways.
__global__ __launch_bounds__(256) void k_transpose(const float* __restrict__ cls) {
    __shared__ float s[NC * 33];
    const int p0 = blockIdx.x * 32;
    // read: 32 rows x 20 float4
    for (int i = threadIdx.x; i < 32 * (NC / 4); i += 256) {
        int r  = i / (NC / 4);
        int c4 = i - r * (NC / 4);
        int p  = p0 + r;
        float4 v = (p < PQ) ? *(const float4*)(cls + (size_t)p * NC + c4 * 4)
                            : make_float4(0.f, 0.f, 0.f, 0.f);
        s[(c4 * 4 + 0) * 33 + r] = v.x;
        s[(c4 * 4 + 1) * 33 + r] = v.y;
        s[(c4 * 4 + 2) * 33 + r] = v.z;
        s[(c4 * 4 + 3) * 33 + r] = v.w;
    }
    __syncthreads();
    // write: 80 rows x 32 consecutive floats (128B per warp-row, coalesced)
    for (int i = threadIdx.x; i < NC * 32; i += 256) {
        int row = i >> 5;
        int col = i & 31;
        int p = p0 + col;
        if (p < PQ) g_clsT[(size_t)row * PQ + p] = s[row * 33 + col];
    }
}

// Stage 1: warp-per-gt, lanes-per-priors, warp-collective distributed top-13.
// Lanes 0..12 hold the sorted (desc) top-13; lane 12 = running threshold.
__global__ __launch_bounds__(256) void k_stage1(const float4* __restrict__ pbox,
                                                const int*    __restrict__ lblg,
                                                const float4* __restrict__ gbox) {
    __shared__ float4 s_box[SUB];
    const int warp = threadIdx.x >> 5;
    const int lane = threadIdx.x & 31;
    const int g = blockIdx.y * GPB + warp;
    const int chunk = blockIdx.x;
    const int base0 = chunk * CHK;

    const float4 gb = gbox[g];
    const int cg = lblg[g] - 1;
    const float ga = fmaxf(gb.z - gb.x, 0.f) * fmaxf(gb.w - gb.y, 0.f);
    const float* __restrict__ crow = g_clsT + (size_t)cg * PQ;

    unsigned long long list = 0ULL;   // lane<13: slot in distributed sorted list

    for (int sub = 0; sub < CHK / SUB; sub++) {
        const int sbase = base0 + sub * SUB;
        __syncthreads();
        for (int i = threadIdx.x; i < SUB; i += 256) {
            int p = sbase + i;
            s_box[i] = (p < PQ) ? pbox[p] : make_float4(0.f, 0.f, 0.f, 0.f);
        }
        __syncthreads();

        for (int r = 0; r < SUB / 32; r++) {
            const int idx = (r << 5) + lane;
            const int p = sbase + idx;
            const float s = (p < PQ) ? __ldg(crow + p) : 0.f;
            const float4 b = s_box[idx];
            float x1 = fmaxf(gb.x, b.x), y1 = fmaxf(gb.y, b.y);
            float x2 = fminf(gb.z, b.z), y2 = fminf(gb.w, b.w);
            float iw = fmaxf(x2 - x1, 0.f), ih = fmaxf(y2 - y1, 0.f);
            float inter = iw * ih;
            float a2 = fmaxf(b.z - b.x, 0.f) * fmaxf(b.w - b.y, 0.f);
            float iou = inter / (ga + a2 - inter + EPSF);
            float i2 = iou * iou;
            float m = s * (i2 * i2 * i2);
            unsigned long long key = (p < PQ)
                ? (((unsigned long long)__float_as_uint(m) << 32) | (unsigned)(~(unsigned)p))
                : 0ULL;

            unsigned long long thr = __shfl_sync(FULL, list, 12);
            unsigned bal = __ballot_sync(FULL, key > thr);
            while (bal) {
                int src = __ffs(bal) - 1;
                bal &= bal - 1;
                unsigned long long k = __shfl_sync(FULL, key, src);
                // insertion position = #elements greater than k (unique keys)
                unsigned gm = __ballot_sync(FULL, lane < TK && list > k);
                int pos = __popc(gm);
                unsigned long long up = __shfl_up_sync(FULL, list, 1);
                if (lane < TK) {
                    if (lane == pos) list = k;        // pos==13 -> no lane matches, no-op
                    else if (lane > pos) list = up;
                }
            }
        }
    }
    if (lane < TK)
        g_cand[((size_t)g * NCH + chunk) * TK + lane] = list;
}

// Stage 2: warp-per-gt merge of 481 candidates -> top-13, scatter folded in.
__global__ __launch_bounds__(256) void k_stage2() {
    __shared__ unsigned long long s[GPB][512];
    const int warp = threadIdx.x >> 5;
    const int lane = threadIdx.x & 31;
    const int g = blockIdx.x * GPB + warp;

    for (int i = lane; i < 512; i += 32)
        s[warp][i] = (i < M2) ? g_cand[(size_t)g * M2 + i] : 0ULL;
    __syncwarp();

    int keep = 1;
    for (int round = 0; round < TK; round++) {
        unsigned long long mymax = 0ULL;
        int myidx = -1;
        for (int i = lane; i < 512; i += 32) {
            unsigned long long v = s[warp][i];
            if (v > mymax) { mymax = v; myidx = i; }
        }
        unsigned long long wmax = mymax;
        for (int off = 16; off > 0; off >>= 1)
            wmax = umax64(wmax, __shfl_xor_sync(FULL, wmax, off));
        if (round == 0)
            keep = (__uint_as_float((unsigned)(wmax >> 32)) > EPSF) ? 1 : 0;
        // owner zeroes its slot (keys unique & nonzero within 13 rounds)
        unsigned own = __ballot_sync(FULL, mymax == wmax);
        if (lane == (__ffs(own) - 1)) {
            s[warp][myidx] = 0ULL;
            if (keep) {
                int p = (int)(~(unsigned)wmax);
                atomicAdd(&g_cnt[p], 1);
                atomicMin(&g_first[p], g);
            }
        }
        __syncwarp();
    }
}

// Final per-prior resolution + writes of gt_idx, labels, bboxes.
__global__ __launch_bounds__(256) void k_final(const float4* __restrict__ pbox,
                                               const int*    __restrict__ lblg,
                                               const float4* __restrict__ gbox,
                                               float*        __restrict__ out) {
    __shared__ float4 s_g[NGT];
    __shared__ float  s_ga[NGT];
    const int tid = threadIdx.x;
    {
        float4 q = gbox[tid];
        s_g[tid] = q;
        s_ga[tid] = fmaxf(q.z - q.x, 0.f) * fmaxf(q.w - q.y, 0.f);
    }
    __syncthreads();
    const int p = blockIdx.x * 256 + tid;
    if (p >= PQ) return;

    const int c = g_cnt[p];
    int gt = 0;
    if (c == 1) {
        gt = g_first[p];
    } else if (c > 1) {
        float4 b = pbox[p];
        float a2 = fmaxf(b.z - b.x, 0.f) * fmaxf(b.w - b.y, 0.f);
        float best = -1.f; int bg = 0;
        for (int g = 0; g < NGT; g++) {
            float4 gb = s_g[g];
            float x1 = fmaxf(gb.x, b.x), y1 = fmaxf(gb.y, b.y);
            float x2 = fminf(gb.z, b.z), y2 = fminf(gb.w, b.w);
            float iw = fmaxf(x2 - x1, 0.f), ih = fmaxf(y2 - y1, 0.f);
            float inter = iw * ih;
            float iou = inter / (s_ga[g] + a2 - inter + EPSF);
            if (iou > best) { best = iou; bg = g; }
        }
        gt = bg;
    }
    const int lab = lblg[gt];
    out[p] = (float)gt;
    out[(size_t)PQ + p] = (c > 0) ? (float)lab : 0.f;
    g_labm1[p] = lab - 1;
    ((float4*)(out + 2 * (size_t)PQ + (size_t)NC * PQ))[p] = s_g[gt];
}

// One-hot cls: coalesced float4 stores of the 48MB block.
__global__ void k_cls(float* __restrict__ out) {
    int i = blockIdx.x * blockDim.x + threadIdx.x;
    if (i >= PQ * (NC / 4)) return;
    int p  = i / (NC / 4);
    int q4 = i - p * (NC / 4);
    int lm = g_labm1[p];
    int base = q4 * 4;
    float4 v;
    v.x = (lm == base + 0) ? 1.f : 0.f;
    v.y = (lm == base + 1) ? 1.f : 0.f;
    v.z = (lm == base + 2) ? 1.f : 0.f;
    v.w = (lm == base + 3) ? 1.f : 0.f;
    ((float4*)(out + 2 * (size_t)PQ))[i] = v;
}

extern "C" void kernel_launch(void* const* d_in, const int* in_sizes, int n_in,
                              void* d_out, int out_size) {
    const float*  cls  = (const float*)d_in[0];   // [P,80]
    const float4* pbox = (const float4*)d_in[1];  // [P,4]
    const int*    lblg = (const int*)d_in[2];     // [N,1]
    const float4* gbox = (const float4*)d_in[3];  // [N,4]
    float* out = (float*)d_out;

    k_init<<<(PQ + 255) / 256, 256>>>();
    k_transpose<<<(PQ + 31) / 32, 256>>>(cls);
    dim3 g1(NCH, NGT / GPB);
    k_stage1<<<g1, 256>>>(pbox, lblg, gbox);
    k_stage2<<<NGT / GPB, 256>>>();
    k_final<<<(PQ + 255) / 256, 256>>>(pbox, lblg, gbox, out);
    k_cls<<<(PQ * (NC / 4) + 255) / 256, 256>>>(out);
}

// round 12
// speedup vs baseline: 1.5293x; 1.1190x over previous
#include <cuda_runtime.h>

#define PQ   150000
#define NGT  256
#define NC   80
#define TK   13
#define CHK  4096                      // priors per stage1 chunk
#define SUB  1024                      // smem box sub-tile
#define NCH  ((PQ + CHK - 1) / CHK)    // 37 chunks
#define M2   (NCH * TK)                // 481 candidates per gt
#define GPB  8                         // gts (warps) per stage1 block
#define EPSF 1e-9f
#define FULL 0xFFFFFFFFu
// sentinel: beats every zero-metric key (except p=0's own, chunk 0 only), loses to every m>0 key
#define SENT 0x00000000FFFFFFFFULL

// ---- device scratch (no allocations allowed) ----
__device__ float g_clsT[(size_t)NC * PQ];                 // class-major transpose (48MB)
__device__ unsigned long long g_cand[(size_t)NGT * M2];   // per-(gt,chunk) top-13 keys
__device__ int g_cnt[PQ];
__device__ int g_first[PQ];
__device__ int g_labm1[PQ];

// warp-collective sorted insert into distributed top-13 (lanes 0..12, desc; lane 12 = min).
// Self-guarding: a key smaller than all 13 entries computes pos==13 -> no lane writes -> no-op.
static __device__ __forceinline__ void warp_insert(unsigned long long& list,
                                                   unsigned long long k, int lane) {
    unsigned gm = __ballot_sync(FULL, lane < TK && list > k);
    int pos = __popc(gm);
    unsigned long long up = __shfl_up_sync(FULL, list, 1);
    if (lane < TK) {
        if (lane == pos) list = k;
        else if (lane > pos) list = up;
    }
}

// Transpose cls [P,80] -> clsT [80,P]; per-prior init fused in. Coalesced both ways.
__global__ __launch_bounds__(256) void k_transpose(const float* __restrict__ cls) {
    __shared__ float s[NC * 33];
    const int p0 = blockIdx.x * 32;
    if (threadIdx.x < 32) {
        int p = p0 + threadIdx.x;
        if (p < PQ) { g_cnt[p] = 0; g_first[p] = 0x7FFFFFFF; }
    }
    for (int i = threadIdx.x; i < 32 * (NC / 4); i += 256) {
        int r  = i / (NC / 4);
        int c4 = i - r * (NC / 4);
        int p  = p0 + r;
        float4 v = (p < PQ) ? *(const float4*)(cls + (size_t)p * NC + c4 * 4)
                            : make_float4(0.f, 0.f, 0.f, 0.f);
        s[(c4 * 4 + 0) * 33 + r] = v.x;
        s[(c4 * 4 + 1) * 33 + r] = v.y;
        s[(c4 * 4 + 2) * 33 + r] = v.z;
        s[(c4 * 4 + 3) * 33 + r] = v.w;
    }
    __syncthreads();
    for (int i = threadIdx.x; i < NC * 32; i += 256) {
        int row = i >> 5;
        int col = i & 31;
        int p = p0 + col;
        if (p < PQ) g_clsT[(size_t)row * PQ + p] = s[row * 33 + col];
    }
}

// Stage 1: warp-per-gt, lanes-per-priors, warp-collective distributed top-13.
// Lanes 0..12 hold the sorted (desc) top-13; lane 12 = running threshold.
__global__ __launch_bounds__(256) void k_stage1(const float4* __restrict__ pbox,
                                                const int*    __restrict__ lblg,
                                                const float4* __restrict__ gbox) {
    __shared__ float4 s_box[SUB];
    const int warp = threadIdx.x >> 5;
    const int lane = threadIdx.x & 31;
    const int g = blockIdx.y * GPB + warp;
    const int chunk = blockIdx.x;
    const int base0 = chunk * CHK;

    const float4 gb = gbox[g];
    const int cg = lblg[g] - 1;
    const float ga = fmaxf(gb.z - gb.x, 0.f) * fmaxf(gb.w - gb.y, 0.f);
    const float* __restrict__ crow = g_clsT + (size_t)cg * PQ;

    // chunk 0: plain-zero init preserves zero-metric smallest-index fill semantics;
    // chunks>0: SENT suppresses all zero-metric inserts (the R5 cascade).
    unsigned long long list = (chunk == 0) ? 0ULL : SENT;

    for (int sub = 0; sub < CHK / SUB; sub++) {
        const int sbase = base0 + sub * SUB;
        __syncthreads();
        for (int i = threadIdx.x; i < SUB; i += 256) {
            int p = sbase + i;
            s_box[i] = (p < PQ) ? pbox[p] : make_float4(0.f, 0.f, 0.f, 0.f);
        }
        __syncthreads();

        for (int r = 0; r < SUB / 32; r++) {
            const int idx = (r << 5) + lane;
            const int p = sbase + idx;
            const float s = (p < PQ) ? __ldg(crow + p) : 0.f;
            const float4 b = s_box[idx];
            float x1 = fmaxf(gb.x, b.x), y1 = fmaxf(gb.y, b.y);
            float x2 = fminf(gb.z, b.z), y2 = fminf(gb.w, b.w);
            float iw = fmaxf(x2 - x1, 0.f), ih = fmaxf(y2 - y1, 0.f);
            float inter = iw * ih;
            float a2 = fmaxf(b.z - b.x, 0.f) * fmaxf(b.w - b.y, 0.f);
            float iou = __fdividef(inter, ga + a2 - inter + EPSF);
            float i2 = iou * iou;
            float m = s * (i2 * i2 * i2);
            unsigned long long key = (p < PQ)
                ? (((unsigned long long)__float_as_uint(m) << 32) | (unsigned)(~(unsigned)p))
                : 0ULL;

            unsigned long long thr = __shfl_sync(FULL, list, 12);
            unsigned bal = __ballot_sync(FULL, key > thr);
            while (bal) {
                int src = __ffs(bal) - 1;
                bal &= bal - 1;
                unsigned long long k = __shfl_sync(FULL, key, src);
                warp_insert(list, k, lane);
            }
        }
    }
    if (lane < TK)
        g_cand[((size_t)g * NCH + chunk) * TK + lane] = list;
}

// Stage 2: warp-per-gt streaming merge of 481 candidates -> top-13, scatter fused.
__global__ __launch_bounds__(256) void k_stage2() {
    const int warp = threadIdx.x >> 5;
    const int lane = threadIdx.x & 31;
    const int g = blockIdx.x * GPB + warp;
    const unsigned long long* __restrict__ src = g_cand + (size_t)g * M2;

    unsigned long long list = 0ULL;
    for (int it = 0; it < (M2 + 31) / 32; it++) {
        int i = it * 32 + lane;
        unsigned long long key = (i < M2) ? src[i] : 0ULL;
        unsigned long long thr = __shfl_sync(FULL, list, 12);
        unsigned bal = __ballot_sync(FULL, key > thr);
        while (bal) {
            int s = __ffs(bal) - 1;
            bal &= bal - 1;
            unsigned long long k = __shfl_sync(FULL, key, s);
            warp_insert(list, k, lane);
        }
    }
    unsigned long long best = __shfl_sync(FULL, list, 0);
    int keep = __uint_as_float((unsigned)(best >> 32)) > EPSF;
    if (keep && lane < TK) {
        int p = (int)(~(unsigned)list);
        atomicAdd(&g_cnt[p], 1);
        atomicMin(&g_first[p], g);
    }
}

// Final per-prior resolution + writes of gt_idx, labels, bboxes.
__global__ __launch_bounds__(256) void k_final(const float4* __restrict__ pbox,
                                               const int*    __restrict__ lblg,
                                               const float4* __restrict__ gbox,
                                               float*        __restrict__ out) {
    __shared__ float4 s_g[NGT];
    __shared__ float  s_ga[NGT];
    const int tid = threadIdx.x;
    {
        float4 q = gbox[tid];
        s_g[tid] = q;
        s_ga[tid] = fmaxf(q.z - q.x, 0.f) * fmaxf(q.w - q.y, 0.f);
    }
    __syncthreads();
    const int p = blockIdx.x * 256 + tid;
    if (p >= PQ) return;

    const int c = g_cnt[p];
    int gt = 0;
    if (c == 1) {
        gt = g_first[p];
    } else if (c > 1) {
        float4 b = pbox[p];
        float a2 = fmaxf(b.z - b.x, 0.f) * fmaxf(b.w - b.y, 0.f);
        float best = -1.f; int bg = 0;
        for (int g = 0; g < NGT; g++) {
            float4 gb = s_g[g];
            float x1 = fmaxf(gb.x, b.x), y1 = fmaxf(gb.y, b.y);
            float x2 = fminf(gb.z, b.z), y2 = fminf(gb.w, b.w);
            float iw = fmaxf(x2 - x1, 0.f), ih = fmaxf(y2 - y1, 0.f);
            float inter = iw * ih;
            float iou = inter / (s_ga[g] + a2 - inter + EPSF);
            if (iou > best) { best = iou; bg = g; }
        }
        gt = bg;
    }
    const int lab = lblg[gt];
    out[p] = (float)gt;
    out[(size_t)PQ + p] = (c > 0) ? (float)lab : 0.f;
    g_labm1[p] = lab - 1;
    ((float4*)(out + 2 * (size_t)PQ + (size_t)NC * PQ))[p] = s_g[gt];
}

// One-hot cls: coalesced float4 stores of the 48MB block.
__global__ void k_cls(float* __restrict__ out) {
    int i = blockIdx.x * blockDim.x + threadIdx.x;
    if (i >= PQ * (NC / 4)) return;
    int p  = i / (NC / 4);
    int q4 = i - p * (NC / 4);
    int lm = g_labm1[p];
    int base = q4 * 4;
    float4 v;
    v.x = (lm == base + 0) ? 1.f : 0.f;
    v.y = (lm == base + 1) ? 1.f : 0.f;
    v.z = (lm == base + 2) ? 1.f : 0.f;
    v.w = (lm == base + 3) ? 1.f : 0.f;
    ((float4*)(out + 2 * (size_t)PQ))[i] = v;
}

extern "C" void kernel_launch(void* const* d_in, const int* in_sizes, int n_in,
                              void* d_out, int out_size) {
    const float*  cls  = (const float*)d_in[0];   // [P,80]
    const float4* pbox = (const float4*)d_in[1];  // [P,4]
    const int*    lblg = (const int*)d_in[2];     // [N,1]
    const float4* gbox = (const float4*)d_in[3];  // [N,4]
    float* out = (float*)d_out;

    k_transpose<<<(PQ + 31) / 32, 256>>>(cls);    // init fused
    dim3 g1(NCH, NGT / GPB);
    k_stage1<<<g1, 256>>>(pbox, lblg, gbox);
    k_stage2<<<NGT / GPB, 256>>>();
    k_final<<<(PQ + 255) / 256, 256>>>(pbox, lblg, gbox, out);
    k_cls<<<(PQ * (NC / 4) + 255) / 256, 256>>>(out);
}

// round 13
// speedup vs baseline: 2.1598x; 1.4123x over previous
#include <cuda_runtime.h>

#define PQ   150000
#define NGT  256
#define NC   80
#define TK   13
#define CHK  4096                      // priors per stage1 chunk
#define SUB  1024                      // smem box sub-tile
#define NCH  ((PQ + CHK - 1) / CHK)    // 37 chunks
#define M2   (NCH * TK)                // 481 candidates per gt
#define GPB  8                         // gts (warps) per stage1 block
#define MAXCONF (NGT * TK / 2)         // 1664 upper bound on conflicted priors
#define EPSF 1e-9f
#define FULL 0xFFFFFFFFu
// sentinel: beats every zero-metric key, loses to every m>0 key (chunk 0 keeps 0-init)
#define SENT 0x00000000FFFFFFFFULL

// ---- device scratch (no allocations allowed) ----
__device__ float g_clsT[(size_t)NC * PQ];                 // class-major transpose (48MB)
__device__ unsigned long long g_cand[(size_t)NGT * M2];   // per-(gt,chunk) top-13 keys
__device__ int g_cnt[PQ];
__device__ int g_first[PQ];
__device__ int g_labm1[PQ];
__device__ int g_conf[MAXCONF];
__device__ int g_nconf;

// warp-collective sorted insert into distributed top-13 (lanes 0..12, desc; lane 12 = min).
// Self-guarding: key below all 13 entries -> pos==13 -> no lane writes -> no-op.
static __device__ __forceinline__ void warp_insert(unsigned long long& list,
                                                   unsigned long long k, int lane) {
    unsigned gm = __ballot_sync(FULL, lane < TK && list > k);
    int pos = __popc(gm);
    unsigned long long up = __shfl_up_sync(FULL, list, 1);
    if (lane < TK) {
        if (lane == pos) list = k;
        else if (lane > pos) list = up;
    }
}

// Transpose cls [P,80] -> clsT [80,P]; per-prior init fused in. Coalesced both ways.
__global__ __launch_bounds__(256) void k_transpose(const float* __restrict__ cls) {
    __shared__ float s[NC * 33];
    const int p0 = blockIdx.x * 32;
    if (blockIdx.x == 0 && threadIdx.x == 0) g_nconf = 0;
    if (threadIdx.x < 32) {
        int p = p0 + threadIdx.x;
        if (p < PQ) { g_cnt[p] = 0; g_first[p] = 0x7FFFFFFF; }
    }
    for (int i = threadIdx.x; i < 32 * (NC / 4); i += 256) {
        int r  = i / (NC / 4);
        int c4 = i - r * (NC / 4);
        int p  = p0 + r;
        float4 v = (p < PQ) ? *(const float4*)(cls + (size_t)p * NC + c4 * 4)
                            : make_float4(0.f, 0.f, 0.f, 0.f);
        s[(c4 * 4 + 0) * 33 + r] = v.x;
        s[(c4 * 4 + 1) * 33 + r] = v.y;
        s[(c4 * 4 + 2) * 33 + r] = v.z;
        s[(c4 * 4 + 3) * 33 + r] = v.w;
    }
    __syncthreads();
    for (int i = threadIdx.x; i < NC * 32; i += 256) {
        int row = i >> 5;
        int col = i & 31;
        int p = p0 + col;
        if (p < PQ) g_clsT[(size_t)row * PQ + p] = s[row * 33 + col];
    }
}

// Stage 1: warp-per-gt, lanes-per-priors, warp-collective distributed top-13.
__global__ __launch_bounds__(256) void k_stage1(const float4* __restrict__ pbox,
                                                const int*    __restrict__ lblg,
                                                const float4* __restrict__ gbox) {
    __shared__ float4 s_box[SUB];
    const int warp = threadIdx.x >> 5;
    const int lane = threadIdx.x & 31;
    const int g = blockIdx.y * GPB + warp;
    const int chunk = blockIdx.x;
    const int base0 = chunk * CHK;

    const float4 gb = gbox[g];
    const int cg = lblg[g] - 1;
    const float ga = fmaxf(gb.z - gb.x, 0.f) * fmaxf(gb.w - gb.y, 0.f);
    const float* __restrict__ crow = g_clsT + (size_t)cg * PQ;

    unsigned long long list = (chunk == 0) ? 0ULL : SENT;
    unsigned long long thr = __shfl_sync(FULL, list, 12);   // hoisted; refreshed on insert

    for (int sub = 0; sub < CHK / SUB; sub++) {
        const int sbase = base0 + sub * SUB;
        __syncthreads();
        for (int i = threadIdx.x; i < SUB; i += 256) {
            int p = sbase + i;
            s_box[i] = (p < PQ) ? pbox[p] : make_float4(0.f, 0.f, 0.f, 0.f);
        }
        __syncthreads();

        for (int r = 0; r < SUB / 32; r++) {
            const int idx = (r << 5) + lane;
            const int p = sbase + idx;
            const float s = (p < PQ) ? __ldg(crow + p) : 0.f;
            const float4 b = s_box[idx];
            float x1 = fmaxf(gb.x, b.x), y1 = fmaxf(gb.y, b.y);
            float x2 = fminf(gb.z, b.z), y2 = fminf(gb.w, b.w);
            float iw = fmaxf(x2 - x1, 0.f), ih = fmaxf(y2 - y1, 0.f);
            float inter = iw * ih;
            float a2 = fmaxf(b.z - b.x, 0.f) * fmaxf(b.w - b.y, 0.f);
            float iou = __fdividef(inter, ga + a2 - inter + EPSF);
            float i2 = iou * iou;
            float m = s * (i2 * i2 * i2);
            unsigned long long key = (p < PQ)
                ? (((unsigned long long)__float_as_uint(m) << 32) | (unsigned)(~(unsigned)p))
                : 0ULL;

            unsigned bal = __ballot_sync(FULL, key > thr);
            while (bal) {
                int src = __ffs(bal) - 1;
                bal &= bal - 1;
                unsigned long long k = __shfl_sync(FULL, key, src);
                warp_insert(list, k, lane);
                thr = __shfl_sync(FULL, list, 12);
            }
        }
    }
    if (lane < TK)
        g_cand[((size_t)g * NCH + chunk) * TK + lane] = list;
}

// Stage 2: warp-per-gt streaming merge of 481 candidates -> top-13; scatter + conflict queue fused.
__global__ __launch_bounds__(256) void k_stage2() {
    const int warp = threadIdx.x >> 5;
    const int lane = threadIdx.x & 31;
    const int g = blockIdx.x * GPB + warp;
    const unsigned long long* __restrict__ src = g_cand + (size_t)g * M2;

    unsigned long long list = 0ULL;
    unsigned long long thr = 0ULL;
    for (int it = 0; it < (M2 + 31) / 32; it++) {
        int i = it * 32 + lane;
        unsigned long long key = (i < M2) ? src[i] : 0ULL;
        unsigned bal = __ballot_sync(FULL, key > thr);
        while (bal) {
            int s = __ffs(bal) - 1;
            bal &= bal - 1;
            unsigned long long k = __shfl_sync(FULL, key, s);
            warp_insert(list, k, lane);
            thr = __shfl_sync(FULL, list, 12);
        }
    }
    unsigned long long best = __shfl_sync(FULL, list, 0);
    int keep = __uint_as_float((unsigned)(best >> 32)) > EPSF;
    if (keep && lane < TK) {
        int p = (int)(~(unsigned)list);
        int old = atomicAdd(&g_cnt[p], 1);
        atomicMin(&g_first[p], g);
        if (old == 1) {                     // 2nd pick: enqueue exactly once
            int qi = atomicAdd(&g_nconf, 1);
            g_conf[qi] = p;
        }
    }
}

// Resolve conflicted priors: warp per prior, division-free iou-argmax over all 256 gts.
__global__ __launch_bounds__(256) void k_resolve(const float4* __restrict__ pbox,
                                                 const float4* __restrict__ gbox) {
    __shared__ float4 s_g[NGT];
    __shared__ float  s_ga[NGT];
    const int tid = threadIdx.x;
    {
        float4 q = gbox[tid];
        s_g[tid] = q;
        s_ga[tid] = fmaxf(q.z - q.x, 0.f) * fmaxf(q.w - q.y, 0.f);
    }
    __syncthreads();
    const int lane = tid & 31;
    const int idx = blockIdx.x * 8 + (tid >> 5);
    if (idx >= g_nconf) return;
    const int p = g_conf[idx];
    const float4 b = pbox[p];                              // warp-broadcast load
    const float a2 = fmaxf(b.z - b.x, 0.f) * fmaxf(b.w - b.y, 0.f);

    // best ratio bi/bu; cross-multiply compare preserves ordering without division
    float bi = -1.f, bu = 1.f; int bg = 0;
    for (int g = lane; g < NGT; g += 32) {
        float4 gb = s_g[g];
        float x1 = fmaxf(gb.x, b.x), y1 = fmaxf(gb.y, b.y);
        float x2 = fminf(gb.z, b.z), y2 = fminf(gb.w, b.w);
        float iw = fmaxf(x2 - x1, 0.f), ih = fmaxf(y2 - y1, 0.f);
        float inter = iw * ih;
        float uni = s_ga[g] + a2 - inter + EPSF;
        if (inter * bu > bi * uni) { bi = inter; bu = uni; bg = g; }  // strict > keeps lowest g
    }
    for (int off = 16; off > 0; off >>= 1) {
        float oi = __shfl_down_sync(FULL, bi, off);
        float ou = __shfl_down_sync(FULL, bu, off);
        int   og = __shfl_down_sync(FULL, bg, off);
        float l = oi * bu, r = bi * ou;
        if (l > r || (l == r && og < bg)) { bi = oi; bu = ou; bg = og; }
    }
    if (lane == 0) g_first[p] = bg;       // overwrite with iou-argmax winner
}

// Final per-prior streaming writes (branch-free; conflicts pre-resolved).
__global__ __launch_bounds__(256) void k_final(const int*    __restrict__ lblg,
                                               const float4* __restrict__ gbox,
                                               float*        __restrict__ out) {
    __shared__ float4 s_g[NGT];
    const int tid = threadIdx.x;
    s_g[tid] = gbox[tid];
    __syncthreads();
    const int p = blockIdx.x * 256 + tid;
    if (p >= PQ) return;

    const int c = g_cnt[p];
    const int gt = (c > 0) ? g_first[p] : 0;
    const int lab = lblg[gt];
    out[p] = (float)gt;
    out[(size_t)PQ + p] = (c > 0) ? (float)lab : 0.f;
    g_labm1[p] = lab - 1;
    ((float4*)(out + 2 * (size_t)PQ + (size_t)NC * PQ))[p] = s_g[gt];
}

// One-hot cls: coalesced float4 stores of the 48MB block.
__global__ void k_cls(float* __restrict__ out) {
    int i = blockIdx.x * blockDim.x + threadIdx.x;
    if (i >= PQ * (NC / 4)) return;
    int p  = i / (NC / 4);
    int q4 = i - p * (NC / 4);
    int lm = g_labm1[p];
    int base = q4 * 4;
    float4 v;
    v.x = (lm == base + 0) ? 1.f : 0.f;
    v.y = (lm == base + 1) ? 1.f : 0.f;
    v.z = (lm == base + 2) ? 1.f : 0.f;
    v.w = (lm == base + 3) ? 1.f : 0.f;
    ((float4*)(out + 2 * (size_t)PQ))[i] = v;
}

extern "C" void kernel_launch(void* const* d_in, const int* in_sizes, int n_in,
                              void* d_out, int out_size) {
    const float*  cls  = (const float*)d_in[0];   // [P,80]
    const float4* pbox = (const float4*)d_in[1];  // [P,4]
    const int*    lblg = (const int*)d_in[2];     // [N,1]
    const float4* gbox = (const float4*)d_in[3];  // [N,4]
    float* out = (float*)d_out;

    k_transpose<<<(PQ + 31) / 32, 256>>>(cls);    // init + queue reset fused
    dim3 g1(NCH, NGT / GPB);
    k_stage1<<<g1, 256>>>(pbox, lblg, gbox);
    k_stage2<<<NGT / GPB, 256>>>();
    k_resolve<<<(MAXCONF + 7) / 8, 256>>>(pbox, gbox);
    k_final<<<(PQ + 255) / 256, 256>>>(lblg, gbox, out);
    k_cls<<<(PQ * (NC / 4) + 255) / 256, 256>>>(out);
}

// round 14
// speedup vs baseline: 2.5558x; 1.1834x over previous
#include <cuda_runtime.h>

#define PQ   150000
#define NGT  256
#define NC   80
#define TK   13
#define CHK  4096                      // priors per stage1 chunk
#define SUB  1024                      // smem box sub-tile
#define NCH  ((PQ + CHK - 1) / CHK)    // 37 chunks
#define M2   (NCH * TK)                // 481 candidates per gt
#define GPB  8                         // gts (warps) per stage1 block
#define MAXCONF (NGT * TK / 2)         // 1664 upper bound on conflicted priors
#define EPSF 1e-9f
#define FULL 0xFFFFFFFFu
// sentinel: beats every zero-metric key, loses to every m>0 key (chunk 0 keeps 0-init)
#define SENT 0x00000000FFFFFFFFULL

// ---- device scratch (no allocations allowed; zero-initialized at load) ----
__device__ float g_clsT[(size_t)NC * PQ + CHK];           // +pad: vectorized tail reads stay in-bounds
__device__ unsigned long long g_cand[(size_t)NGT * M2];   // per-(gt,chunk) top-13 keys
__device__ int g_cnt[PQ];
__device__ int g_first[PQ];
__device__ int g_labm1[PQ];
__device__ int g_conf[MAXCONF];
__device__ int g_nconf;

// warp-collective sorted insert into distributed top-13 (lanes 0..12, desc; lane 12 = min).
// Self-guarding: key below all 13 entries -> pos==13 -> no lane writes -> no-op.
static __device__ __forceinline__ void warp_insert(unsigned long long& list,
                                                   unsigned long long k, int lane) {
    unsigned gm = __ballot_sync(FULL, lane < TK && list > k);
    int pos = __popc(gm);
    unsigned long long up = __shfl_up_sync(FULL, list, 1);
    if (lane < TK) {
        if (lane == pos) list = k;
        else if (lane > pos) list = up;
    }
}

// Transpose cls [P,80] -> clsT [80,P]; per-prior init fused in. Coalesced both ways.
__global__ __launch_bounds__(256) void k_transpose(const float* __restrict__ cls) {
    __shared__ float s[NC * 33];
    const int p0 = blockIdx.x * 32;
    if (blockIdx.x == 0 && threadIdx.x == 0) g_nconf = 0;
    if (threadIdx.x < 32) {
        int p = p0 + threadIdx.x;
        if (p < PQ) { g_cnt[p] = 0; g_first[p] = 0x7FFFFFFF; }
    }
    for (int i = threadIdx.x; i < 32 * (NC / 4); i += 256) {
        int r  = i / (NC / 4);
        int c4 = i - r * (NC / 4);
        int p  = p0 + r;
        float4 v = (p < PQ) ? *(const float4*)(cls + (size_t)p * NC + c4 * 4)
                            : make_float4(0.f, 0.f, 0.f, 0.f);
        s[(c4 * 4 + 0) * 33 + r] = v.x;
        s[(c4 * 4 + 1) * 33 + r] = v.y;
        s[(c4 * 4 + 2) * 33 + r] = v.z;
        s[(c4 * 4 + 3) * 33 + r] = v.w;
    }
    __syncthreads();
    for (int i = threadIdx.x; i < NC * 32; i += 256) {
        int row = i >> 5;
        int col = i & 31;
        int p = p0 + col;
        if (p < PQ) g_clsT[(size_t)row * PQ + p] = s[row * 33 + col];
    }
}

// Stage 1: warp-per-gt, 4 priors per lane per iteration, warp-collective distributed top-13.
__global__ __launch_bounds__(256) void k_stage1(const float4* __restrict__ pbox,
                                                const int*    __restrict__ lblg,
                                                const float4* __restrict__ gbox) {
    __shared__ __align__(16) float s_x1[SUB], s_y1[SUB], s_x2[SUB], s_y2[SUB];
    const int warp = threadIdx.x >> 5;
    const int lane = threadIdx.x & 31;
    const int g = blockIdx.y * GPB + warp;
    const int chunk = blockIdx.x;
    const int base0 = chunk * CHK;

    const float4 gb = gbox[g];
    const int cg = lblg[g] - 1;
    const float ga = fmaxf(gb.z - gb.x, 0.f) * fmaxf(gb.w - gb.y, 0.f);
    const float* __restrict__ crow = g_clsT + (size_t)cg * PQ;

    // chunk 0: zero-init preserves zero-metric smallest-index fill semantics;
    // chunks>0: SENT suppresses all zero-metric inserts.
    unsigned long long list = (chunk == 0) ? 0ULL : SENT;
    unsigned long long thr = __shfl_sync(FULL, list, 12);

    for (int sub = 0; sub < CHK / SUB; sub++) {
        const int sbase = base0 + sub * SUB;
        __syncthreads();
        for (int i = threadIdx.x; i < SUB; i += 256) {
            int p = sbase + i;
            float4 b = (p < PQ) ? pbox[p] : make_float4(0.f, 0.f, 0.f, 0.f);
            s_x1[i] = b.x; s_y1[i] = b.y; s_x2[i] = b.z; s_y2[i] = b.w;
        }
        __syncthreads();

#pragma unroll 2
        for (int r = 0; r < SUB / 128; r++) {
            const int i4 = (r << 7) + (lane << 2);
            const int p0 = sbase + i4;
            // pad guarantees in-bounds for the tail; pad values are 0 -> m=0 keys lose to SENT
            float4 cx  = *(const float4*)(crow + p0);
            float4 bx1 = *(const float4*)(s_x1 + i4);
            float4 by1 = *(const float4*)(s_y1 + i4);
            float4 bx2 = *(const float4*)(s_x2 + i4);
            float4 by2 = *(const float4*)(s_y2 + i4);
            float sc[4]  = {cx.x, cx.y, cx.z, cx.w};
            float vx1[4] = {bx1.x, bx1.y, bx1.z, bx1.w};
            float vy1[4] = {by1.x, by1.y, by1.z, by1.w};
            float vx2[4] = {bx2.x, bx2.y, bx2.z, bx2.w};
            float vy2[4] = {by2.x, by2.y, by2.z, by2.w};

            unsigned long long kk[4];
#pragma unroll
            for (int j = 0; j < 4; j++) {
                float x1 = fmaxf(gb.x, vx1[j]), y1 = fmaxf(gb.y, vy1[j]);
                float x2 = fminf(gb.z, vx2[j]), y2 = fminf(gb.w, vy2[j]);
                float iw = fmaxf(x2 - x1, 0.f), ih = fmaxf(y2 - y1, 0.f);
                float inter = iw * ih;
                float a2 = fmaxf(vx2[j] - vx1[j], 0.f) * fmaxf(vy2[j] - vy1[j], 0.f);
                float iou = __fdividef(inter, ga + a2 - inter + EPSF);
                float i2 = iou * iou;
                float m = sc[j] * (i2 * i2 * i2);
                kk[j] = ((unsigned long long)__float_as_uint(m) << 32)
                      | (unsigned)(~(unsigned)(p0 + j));
            }
            unsigned long long lm01 = kk[0] > kk[1] ? kk[0] : kk[1];
            unsigned long long lm23 = kk[2] > kk[3] ? kk[2] : kk[3];
            unsigned long long lm = lm01 > lm23 ? lm01 : lm23;

            if (__ballot_sync(FULL, lm > thr)) {      // rare once threshold warms
#pragma unroll
                for (int j = 0; j < 4; j++) {
                    unsigned bal = __ballot_sync(FULL, kk[j] > thr);
                    while (bal) {
                        int src = __ffs(bal) - 1;
                        bal &= bal - 1;
                        unsigned long long k = __shfl_sync(FULL, kk[j], src);
                        if (k > thr) {                // warp-uniform re-check vs risen thr
                            warp_insert(list, k, lane);
                            thr = __shfl_sync(FULL, list, 12);
                        }
                    }
                }
            }
        }
    }
    if (lane < TK)
        g_cand[((size_t)g * NCH + chunk) * TK + lane] = list;
}

// Stage 2: warp-per-gt streaming merge of 481 candidates -> top-13; scatter + conflict queue fused.
__global__ __launch_bounds__(256) void k_stage2() {
    const int warp = threadIdx.x >> 5;
    const int lane = threadIdx.x & 31;
    const int g = blockIdx.x * GPB + warp;
    const unsigned long long* __restrict__ src = g_cand + (size_t)g * M2;

    unsigned long long list = 0ULL;
    unsigned long long thr = 0ULL;
    for (int it = 0; it < (M2 + 31) / 32; it++) {
        int i = it * 32 + lane;
        unsigned long long key = (i < M2) ? src[i] : 0ULL;
        unsigned bal = __ballot_sync(FULL, key > thr);
        while (bal) {
            int s = __ffs(bal) - 1;
            bal &= bal - 1;
            unsigned long long k = __shfl_sync(FULL, key, s);
            if (k > thr) {
                warp_insert(list, k, lane);
                thr = __shfl_sync(FULL, list, 12);
            }
        }
    }
    unsigned long long best = __shfl_sync(FULL, list, 0);
    int keep = __uint_as_float((unsigned)(best >> 32)) > EPSF;
    if (keep && lane < TK) {
        int p = (int)(~(unsigned)list);
        int old = atomicAdd(&g_cnt[p], 1);
        atomicMin(&g_first[p], g);
        if (old == 1) {                     // 2nd pick: enqueue exactly once
            int qi = atomicAdd(&g_nconf, 1);
            g_conf[qi] = p;
        }
    }
}

// Resolve conflicted priors: warp per prior, division-free iou-argmax over all 256 gts.
__global__ __launch_bounds__(256) void k_resolve(const float4* __restrict__ pbox,
                                                 const float4* __restrict__ gbox) {
    __shared__ float4 s_g[NGT];
    __shared__ float  s_ga[NGT];
    const int tid = threadIdx.x;
    {
        float4 q = gbox[tid];
        s_g[tid] = q;
        s_ga[tid] = fmaxf(q.z - q.x, 0.f) * fmaxf(q.w - q.y, 0.f);
    }
    __syncthreads();
    const int lane = tid & 31;
    const int idx = blockIdx.x * 8 + (tid >> 5);
    if (idx >= g_nconf) return;
    const int p = g_conf[idx];
    const float4 b = pbox[p];
    const float a2 = fmaxf(b.z - b.x, 0.f) * fmaxf(b.w - b.y, 0.f);

    float bi = -1.f, bu = 1.f; int bg = 0;
    for (int g = lane; g < NGT; g += 32) {
        float4 gb = s_g[g];
        float x1 = fmaxf(gb.x, b.x), y1 = fmaxf(gb.y, b.y);
        float x2 = fminf(gb.z, b.z), y2 = fminf(gb.w, b.w);
        float iw = fmaxf(x2 - x1, 0.f), ih = fmaxf(y2 - y1, 0.f);
        float inter = iw * ih;
        float uni = s_ga[g] + a2 - inter + EPSF;
        if (inter * bu > bi * uni) { bi = inter; bu = uni; bg = g; }  // strict > keeps lowest g
    }
    for (int off = 16; off > 0; off >>= 1) {
        float oi = __shfl_down_sync(FULL, bi, off);
        float ou = __shfl_down_sync(FULL, bu, off);
        int   og = __shfl_down_sync(FULL, bg, off);
        float l = oi * bu, r = bi * ou;
        if (l > r || (l == r && og < bg)) { bi = oi; bu = ou; bg = og; }
    }
    if (lane == 0) g_first[p] = bg;
}

// Final per-prior streaming writes (branch-free; conflicts pre-resolved).
__global__ __launch_bounds__(256) void k_final(const int*    __restrict__ lblg,
                                               const float4* __restrict__ gbox,
                                               float*        __restrict__ out) {
    __shared__ float4 s_g[NGT];
    const int tid = threadIdx.x;
    s_g[tid] = gbox[tid];
    __syncthreads();
    const int p = blockIdx.x * 256 + tid;
    if (p >= PQ) return;

    const int c = g_cnt[p];
    const int gt = (c > 0) ? g_first[p] : 0;
    const int lab = lblg[gt];
    out[p] = (float)gt;
    out[(size_t)PQ + p] = (c > 0) ? (float)lab : 0.f;
    g_labm1[p] = lab - 1;
    ((float4*)(out + 2 * (size_t)PQ + (size_t)NC * PQ))[p] = s_g[gt];
}

// One-hot cls: coalesced float4 stores of the 48MB block.
__global__ void k_cls(float* __restrict__ out) {
    int i = blockIdx.x * blockDim.x + threadIdx.x;
    if (i >= PQ * (NC / 4)) return;
    int p  = i / (NC / 4);
    int q4 = i - p * (NC / 4);
    int lm = g_labm1[p];
    int base = q4 * 4;
    float4 v;
    v.x = (lm == base + 0) ? 1.f : 0.f;
    v.y = (lm == base + 1) ? 1.f : 0.f;
    v.z = (lm == base + 2) ? 1.f : 0.f;
    v.w = (lm == base + 3) ? 1.f : 0.f;
    ((float4*)(out + 2 * (size_t)PQ))[i] = v;
}

extern "C" void kernel_launch(void* const* d_in, const int* in_sizes, int n_in,
                              void* d_out, int out_size) {
    const float*  cls  = (const float*)d_in[0];   // [P,80]
    const float4* pbox = (const float4*)d_in[1];  // [P,4]
    const int*    lblg = (const int*)d_in[2];     // [N,1]
    const float4* gbox = (const float4*)d_in[3];  // [N,4]
    float* out = (float*)d_out;

    k_transpose<<<(PQ + 31) / 32, 256>>>(cls);    // init + queue reset fused
    dim3 g1(NCH, NGT / GPB);
    k_stage1<<<g1, 256>>>(pbox, lblg, gbox);
    k_stage2<<<NGT / GPB, 256>>>();
    k_resolve<<<(MAXCONF + 7) / 8, 256>>>(pbox, gbox);
    k_final<<<(PQ + 255) / 256, 256>>>(lblg, gbox, out);
    k_cls<<<(PQ * (NC / 4) + 255) / 256, 256>>>(out);
}

// round 15
// speedup vs baseline: 2.6794x; 1.0484x over previous
#include <cuda_runtime.h>

#define PQ   150000
#define NGT  256
#define NC   80
#define TK   13
#define CHK  8192                      // priors per stage1 chunk
#define SUB  1024                      // smem box sub-tile
#define NCH  ((PQ + CHK - 1) / CHK)    // 19 chunks
#define M2   (NCH * TK)                // 247 candidates per gt
#define GPB  8                         // gts (warps) per stage1 block
#define MAXCONF (NGT * TK / 2)         // 1664 upper bound on conflicted priors
#define EPSF 1e-9f
#define FULL 0xFFFFFFFFu
// sentinel: beats every zero-metric key, loses to every m>0 key (chunk 0 keeps 0-init)
#define SENT 0x00000000FFFFFFFFULL

// ---- device scratch (no allocations allowed; zero-initialized at load) ----
// pad covers vectorized + prefetch reads past PQ (max offset: 79*PQ + NCH*CHK + 128 < NC*PQ + 2*CHK)
__device__ float g_clsT[(size_t)NC * PQ + 2 * CHK];
__device__ unsigned long long g_cand[(size_t)NGT * M2];   // per-(gt,chunk) top-13 keys
__device__ int g_cnt[PQ];
__device__ int g_first[PQ];
__device__ int g_labm1[PQ];
__device__ int g_conf[MAXCONF];
__device__ int g_nconf;

// warp-collective sorted insert into distributed top-13 (lanes 0..12, desc; lane 12 = min).
// Self-guarding: key below all 13 entries -> pos==13 -> no lane writes -> no-op.
static __device__ __forceinline__ void warp_insert(unsigned long long& list,
                                                   unsigned long long k, int lane) {
    unsigned gm = __ballot_sync(FULL, lane < TK && list > k);
    int pos = __popc(gm);
    unsigned long long up = __shfl_up_sync(FULL, list, 1);
    if (lane < TK) {
        if (lane == pos) list = k;
        else if (lane > pos) list = up;
    }
}

// Transpose cls [P,80] -> clsT [80,P]; per-prior init fused in. Coalesced both ways.
__global__ __launch_bounds__(256) void k_transpose(const float* __restrict__ cls) {
    __shared__ float s[NC * 33];
    const int p0 = blockIdx.x * 32;
    if (blockIdx.x == 0 && threadIdx.x == 0) g_nconf = 0;
    if (threadIdx.x < 32) {
        int p = p0 + threadIdx.x;
        if (p < PQ) { g_cnt[p] = 0; g_first[p] = 0x7FFFFFFF; }
    }
    for (int i = threadIdx.x; i < 32 * (NC / 4); i += 256) {
        int r  = i / (NC / 4);
        int c4 = i - r * (NC / 4);
        int p  = p0 + r;
        float4 v = (p < PQ) ? *(const float4*)(cls + (size_t)p * NC + c4 * 4)
                            : make_float4(0.f, 0.f, 0.f, 0.f);
        s[(c4 * 4 + 0) * 33 + r] = v.x;
        s[(c4 * 4 + 1) * 33 + r] = v.y;
        s[(c4 * 4 + 2) * 33 + r] = v.z;
        s[(c4 * 4 + 3) * 33 + r] = v.w;
    }
    __syncthreads();
    for (int i = threadIdx.x; i < NC * 32; i += 256) {
        int row = i >> 5;
        int col = i & 31;
        int p = p0 + col;
        if (p < PQ) g_clsT[(size_t)row * PQ + p] = s[row * 33 + col];
    }
}

// Stage 1: warp-per-gt, 4 priors/lane/iter, software-pipelined cls loads,
// warp-collective distributed top-13.
__global__ __launch_bounds__(256) void k_stage1(const float4* __restrict__ pbox,
                                                const int*    __restrict__ lblg,
                                                const float4* __restrict__ gbox) {
    __shared__ __align__(16) float s_x1[SUB], s_y1[SUB], s_x2[SUB], s_y2[SUB];
    const int warp = threadIdx.x >> 5;
    const int lane = threadIdx.x & 31;
    const int g = blockIdx.y * GPB + warp;
    const int chunk = blockIdx.x;
    const int base0 = chunk * CHK;

    const float4 gb = gbox[g];
    const int cg = lblg[g] - 1;
    const float ga = fmaxf(gb.z - gb.x, 0.f) * fmaxf(gb.w - gb.y, 0.f);
    const float* __restrict__ crow = g_clsT + (size_t)cg * PQ;

    // chunk 0: zero-init preserves zero-metric smallest-index fill semantics;
    // chunks>0: SENT suppresses all zero-metric inserts.
    unsigned long long list = (chunk == 0) ? 0ULL : SENT;
    unsigned long long thr = __shfl_sync(FULL, list, 12);

    // software pipeline: cls vector for the NEXT iteration is always in flight
    float4 cx = *(const float4*)(crow + base0 + (lane << 2));

    for (int sub = 0; sub < CHK / SUB; sub++) {
        const int sbase = base0 + sub * SUB;
        __syncthreads();
        for (int i = threadIdx.x; i < SUB; i += 256) {
            int p = sbase + i;
            float4 b = (p < PQ) ? pbox[p] : make_float4(0.f, 0.f, 0.f, 0.f);
            s_x1[i] = b.x; s_y1[i] = b.y; s_x2[i] = b.z; s_y2[i] = b.w;
        }
        __syncthreads();

#pragma unroll 2
        for (int r = 0; r < SUB / 128; r++) {
            const int i4 = (r << 7) + (lane << 2);
            const int p0 = sbase + i4;
            float4 cur = cx;
            cx = *(const float4*)(crow + p0 + 128);   // prefetch next iter (pad-safe)
            float4 bx1 = *(const float4*)(s_x1 + i4);
            float4 by1 = *(const float4*)(s_y1 + i4);
            float4 bx2 = *(const float4*)(s_x2 + i4);
            float4 by2 = *(const float4*)(s_y2 + i4);
            float sc[4]  = {cur.x, cur.y, cur.z, cur.w};
            float vx1[4] = {bx1.x, bx1.y, bx1.z, bx1.w};
            float vy1[4] = {by1.x, by1.y, by1.z, by1.w};
            float vx2[4] = {bx2.x, bx2.y, bx2.z, bx2.w};
            float vy2[4] = {by2.x, by2.y, by2.z, by2.w};

            unsigned long long kk[4];
#pragma unroll
            for (int j = 0; j < 4; j++) {
                float x1 = fmaxf(gb.x, vx1[j]), y1 = fmaxf(gb.y, vy1[j]);
                float x2 = fminf(gb.z, vx2[j]), y2 = fminf(gb.w, vy2[j]);
                float iw = fmaxf(x2 - x1, 0.f), ih = fmaxf(y2 - y1, 0.f);
                float inter = iw * ih;
                float a2 = fmaxf(vx2[j] - vx1[j], 0.f) * fmaxf(vy2[j] - vy1[j], 0.f);
                float iou = __fdividef(inter, ga + a2 - inter + EPSF);
                float i2 = iou * iou;
                float m = sc[j] * (i2 * i2 * i2);
                kk[j] = ((unsigned long long)__float_as_uint(m) << 32)
                      | (unsigned)(~(unsigned)(p0 + j));
            }
            unsigned long long lm01 = kk[0] > kk[1] ? kk[0] : kk[1];
            unsigned long long lm23 = kk[2] > kk[3] ? kk[2] : kk[3];
            unsigned long long lm = lm01 > lm23 ? lm01 : lm23;

            if (__ballot_sync(FULL, lm > thr)) {      // rare once threshold warms
#pragma unroll
                for (int j = 0; j < 4; j++) {
                    unsigned bal = __ballot_sync(FULL, kk[j] > thr);
                    while (bal) {
                        int src = __ffs(bal) - 1;
                        bal &= bal - 1;
                        unsigned long long k = __shfl_sync(FULL, kk[j], src);
                        if (k > thr) {                // warp-uniform re-check vs risen thr
                            warp_insert(list, k, lane);
                            thr = __shfl_sync(FULL, list, 12);
                        }
                    }
                }
            }
        }
    }
    if (lane < TK)
        g_cand[((size_t)g * NCH + chunk) * TK + lane] = list;
}

// Stage 2: warp-per-gt streaming merge of 247 candidates -> top-13; scatter + conflict queue fused.
__global__ __launch_bounds__(256) void k_stage2() {
    const int warp = threadIdx.x >> 5;
    const int lane = threadIdx.x & 31;
    const int g = blockIdx.x * GPB + warp;
    const unsigned long long* __restrict__ src = g_cand + (size_t)g * M2;

    unsigned long long list = 0ULL;
    unsigned long long thr = 0ULL;
    for (int it = 0; it < (M2 + 31) / 32; it++) {
        int i = it * 32 + lane;
        unsigned long long key = (i < M2) ? src[i] : 0ULL;
        unsigned bal = __ballot_sync(FULL, key > thr);
        while (bal) {
            int s = __ffs(bal) - 1;
            bal &= bal - 1;
            unsigned long long k = __shfl_sync(FULL, key, s);
            if (k > thr) {
                warp_insert(list, k, lane);
                thr = __shfl_sync(FULL, list, 12);
            }
        }
    }
    unsigned long long best = __shfl_sync(FULL, list, 0);
    int keep = __uint_as_float((unsigned)(best >> 32)) > EPSF;
    if (keep && lane < TK) {
        int p = (int)(~(unsigned)list);
        int old = atomicAdd(&g_cnt[p], 1);
        atomicMin(&g_first[p], g);
        if (old == 1) {                     // 2nd pick: enqueue exactly once
            int qi = atomicAdd(&g_nconf, 1);
            g_conf[qi] = p;
        }
    }
}

// Resolve conflicted priors: warp per prior, division-free iou-argmax over all 256 gts.
__global__ __launch_bounds__(256) void k_resolve(const float4* __restrict__ pbox,
                                                 const float4* __restrict__ gbox) {
    __shared__ float4 s_g[NGT];
    __shared__ float  s_ga[NGT];
    const int tid = threadIdx.x;
    {
        float4 q = gbox[tid];
        s_g[tid] = q;
        s_ga[tid] = fmaxf(q.z - q.x, 0.f) * fmaxf(q.w - q.y, 0.f);
    }
    __syncthreads();
    const int lane = tid & 31;
    const int idx = blockIdx.x * 8 + (tid >> 5);
    if (idx >= g_nconf) return;
    const int p = g_conf[idx];
    const float4 b = pbox[p];
    const float a2 = fmaxf(b.z - b.x, 0.f) * fmaxf(b.w - b.y, 0.f);

    float bi = -1.f, bu = 1.f; int bg = 0;
    for (int g = lane; g < NGT; g += 32) {
        float4 gb = s_g[g];
        float x1 = fmaxf(gb.x, b.x), y1 = fmaxf(gb.y, b.y);
        float x2 = fminf(gb.z, b.z), y2 = fminf(gb.w, b.w);
        float iw = fmaxf(x2 - x1, 0.f), ih = fmaxf(y2 - y1, 0.f);
        float inter = iw * ih;
        float uni = s_ga[g] + a2 - inter + EPSF;
        if (inter * bu > bi * uni) { bi = inter; bu = uni; bg = g; }  // strict > keeps lowest g
    }
    for (int off = 16; off > 0; off >>= 1) {
        float oi = __shfl_down_sync(FULL, bi, off);
        float ou = __shfl_down_sync(FULL, bu, off);
        int   og = __shfl_down_sync(FULL, bg, off);
        float l = oi * bu, r = bi * ou;
        if (l > r || (l == r && og < bg)) { bi = oi; bu = ou; bg = og; }
    }
    if (lane == 0) g_first[p] = bg;
}

// Final per-prior streaming writes (branch-free; conflicts pre-resolved).
__global__ __launch_bounds__(256) void k_final(const int*    __restrict__ lblg,
                                               const float4* __restrict__ gbox,
                                               float*        __restrict__ out) {
    __shared__ float4 s_g[NGT];
    const int tid = threadIdx.x;
    s_g[tid] = gbox[tid];
    __syncthreads();
    const int p = blockIdx.x * 256 + tid;
    if (p >= PQ) return;

    const int c = g_cnt[p];
    const int gt = (c > 0) ? g_first[p] : 0;
    const int lab = lblg[gt];
    out[p] = (float)gt;
    out[(size_t)PQ + p] = (c > 0) ? (float)lab : 0.f;
    g_labm1[p] = lab - 1;
    ((float4*)(out + 2 * (size_t)PQ + (size_t)NC * PQ))[p] = s_g[gt];
}

// One-hot cls: coalesced float4 stores of the 48MB block.
__global__ void k_cls(float* __restrict__ out) {
    int i = blockIdx.x * blockDim.x + threadIdx.x;
    if (i >= PQ * (NC / 4)) return;
    int p  = i / (NC / 4);
    int q4 = i - p * (NC / 4);
    int lm = g_labm1[p];
    int base = q4 * 4;
    float4 v;
    v.x = (lm == base + 0) ? 1.f : 0.f;
    v.y = (lm == base + 1) ? 1.f : 0.f;
    v.z = (lm == base + 2) ? 1.f : 0.f;
    v.w = (lm == base + 3) ? 1.f : 0.f;
    ((float4*)(out + 2 * (size_t)PQ))[i] = v;
}

extern "C" void kernel_launch(void* const* d_in, const int* in_sizes, int n_in,
                              void* d_out, int out_size) {
    const float*  cls  = (const float*)d_in[0];   // [P,80]
    const float4* pbox = (const float4*)d_in[1];  // [P,4]
    const int*    lblg = (const int*)d_in[2];     // [N,1]
    const float4* gbox = (const float4*)d_in[3];  // [N,4]
    float* out = (float*)d_out;

    k_transpose<<<(PQ + 31) / 32, 256>>>(cls);    // init + queue reset fused
    dim3 g1(NCH, NGT / GPB);
    k_stage1<<<g1, 256>>>(pbox, lblg, gbox);
    k_stage2<<<NGT / GPB, 256>>>();
    k_resolve<<<(MAXCONF + 7) / 8, 256>>>(pbox, gbox);
    k_final<<<(PQ + 255) / 256, 256>>>(lblg, gbox, out);
    k_cls<<<(PQ * (NC / 4) + 255) / 256, 256>>>(out);
}